// round 12
// baseline (speedup 1.0000x reference)
#include <cuda_runtime.h>
#include <cuda_bf16.h>
#include <cstdint>

// Problem constants
#define Cc 4
#define Bb 2
#define Dd 128
#define NTOK 65536          // F*T per batch
#define TOK 32              // tokens per CTA
#define NTILES 4096         // (Bb*NTOK)/TOK

typedef unsigned long long u64;

// ---------------- composed-weight scratch (device globals: no allocation) ----
__device__ float g_WqT[128 * 128];   // [k][o]  Wq_eff[o][k] = (in_w[0:128] @ Wq)[o][k]
__device__ float g_Wk [128 * 128];   // [r][k]  Wk_eff (row-major)
__device__ float g_WvT[128 * 128];   // [k][r]  Wv_eff transposed
__device__ float g_OwT[128 * 128];   // [o][d]  out_w transposed
__device__ float g_bq [128];         // composed q bias
__device__ float g_bv [128];         // composed v bias

// ---------------- f32x2 / bf16 helpers --------------------------------------
__device__ __forceinline__ u64 ffma2(u64 a, u64 b, u64 c) {
    u64 d;
    asm("fma.rn.f32x2 %0, %1, %2, %3;" : "=l"(d) : "l"(a), "l"(b), "l"(c));
    return d;
}
__device__ __forceinline__ u64 pack2(float lo, float hi) {
    u64 r;
    asm("mov.b64 %0, {%1, %2};" : "=l"(r) : "f"(lo), "f"(hi));
    return r;
}
__device__ __forceinline__ float2 unpack2(u64 v) {
    float2 r;
    asm("mov.b64 {%0, %1}, %2;" : "=f"(r.x), "=f"(r.y) : "l"(v));
    return r;
}
// cvt d, A, B -> d.lo = B, d.hi = A  (per ptx_helpers convention)
__device__ __forceinline__ unsigned pack_bf16x2(float lo, float hi) {
    unsigned r;
    asm("cvt.rn.bf16x2.f32 %0, %1, %2;" : "=r"(r) : "f"(hi), "f"(lo));
    return r;
}
__device__ __forceinline__ unsigned short f2bf(float f) {
    unsigned short h;
    asm("cvt.rn.bf16.f32 %0, %1;" : "=h"(h) : "f"(f));
    return h;
}
__device__ __forceinline__ float bf2f(unsigned short h) {
    return __uint_as_float(((unsigned)h) << 16);
}

// ---------------- prep: compose weights --------------------------------------
__global__ void prep_kernel(const float* __restrict__ Wq, const float* __restrict__ bq,
                            const float* __restrict__ Wk, const float* __restrict__ bk,
                            const float* __restrict__ Wv, const float* __restrict__ bv,
                            const float* __restrict__ in_w, const float* __restrict__ in_b,
                            const float* __restrict__ out_w, const float* __restrict__ out_b) {
    (void)bk; (void)out_b;
    const int blk = blockIdx.x;
    const int t = threadIdx.x;
    if (blk < 128) {
        const int o = blk;
        float acc = 0.f;
        #pragma unroll 8
        for (int m = 0; m < 128; m++) acc += in_w[o * 128 + m] * Wq[m * 128 + t];
        g_WqT[t * 128 + o] = acc;
        if (t == 0) {
            float s = in_b[o];
            for (int m = 0; m < 128; m++) s += in_w[o * 128 + m] * bq[m];
            g_bq[o] = s;
        }
    } else if (blk < 256) {
        const int r = blk - 128;
        float acc = 0.f;
        #pragma unroll 8
        for (int m = 0; m < 128; m++) acc += in_w[(128 + r) * 128 + m] * Wk[m * 128 + t];
        g_Wk[r * 128 + t] = acc;
    } else if (blk < 384) {
        const int r = blk - 256;
        float acc = 0.f;
        #pragma unroll 8
        for (int m = 0; m < 128; m++) acc += in_w[(256 + r) * 128 + m] * Wv[m * 128 + t];
        g_WvT[t * 128 + r] = acc;
        if (t == 0) {
            float s = in_b[256 + r];
            for (int m = 0; m < 128; m++) s += in_w[(256 + r) * 128 + m] * bv[m];
            g_bv[r] = s;
        }
    } else {
        const int d = blk - 384;
        g_OwT[t * 128 + d] = out_w[d * 128 + t];  // OwT[o][d]
    }
}

// ---------------- fused main kernel ------------------------------------------
// smem layout (25344 floats = 101376 B -> 2 CTAs/SM):
//  [0      .. 4096)   s_xq   fp32  q-normalized [d][t]  -> reused as staged out
//  [4096   .. 8192)   s_qf   fp32  qfull/ctx [o][t]     (aliased: LN partials)
//  [8192   .. 16384)  s_x16  bf16  normalized kv [c][d][t]  (16384 elems)
//  [16384  .. 24576)  s_qk16 bf16  qk / mix [h][j][t]       (16384 elems)
//  [24576  .. 25088)  s_sc   scores/attn [t][h][c]
//  [25088  .. 25216)  s_mean [c][t]
//  [25216  .. 25344)  s_rstd [c][t]
__global__ void __launch_bounds__(512, 2)
cca_main(const float* __restrict__ h_all,
         const float* __restrict__ ln_q_g, const float* __restrict__ ln_q_b,
         const float* __restrict__ ln_kv_g, const float* __restrict__ ln_kv_b,
         const float* __restrict__ out_b,
         float* __restrict__ out) {
    extern __shared__ float sm[];
    float* s_xq  = sm;
    float* s_qf  = sm + 4096;
    float* s_ps  = sm + 4096;                 // alias (dead before P2 writes s_qf)
    float* s_pss = sm + 6144;
    unsigned short* s_x16  = (unsigned short*)(sm + 8192);
    unsigned short* s_qk16 = (unsigned short*)(sm + 16384);
    float* s_sc   = sm + 24576;
    float* s_mean = sm + 25088;
    float* s_rstd = sm + 25216;

    const int tid  = threadIdx.x;
    const int w    = tid >> 5;
    const int lane = tid & 31;
    const int tile = blockIdx.x;
    const int b    = tile >> 11;            // 2048 tiles per batch element
    const int tok0 = (tile & 2047) * TOK;

    // ---- P1a: streaming partial LN stats (no raw staging) -------------------
    {
        #pragma unroll
        for (int c = 0; c < 4; c++) {
            const float* src = h_all + (size_t)(c * Bb + b) * Dd * NTOK + tok0 + lane;
            float s = 0.f, ss = 0.f;
            #pragma unroll
            for (int pass = 0; pass < 8; pass++) {
                const int d = pass * 16 + w;
                const float v = __ldg(src + (size_t)d * NTOK);
                s += v; ss += v * v;
            }
            s_ps [(c * 16 + w) * 32 + lane] = s;
            s_pss[(c * 16 + w) * 32 + lane] = ss;
        }
    }
    __syncthreads();

    // ---- P1b: finalize stats (biased variance, eps 1e-5) --------------------
    if (tid < 128) {
        const int c = tid >> 5, t = tid & 31;
        float s = 0.f, ss = 0.f;
        #pragma unroll
        for (int i = 0; i < 16; i++) {
            s  += s_ps [(c * 16 + i) * 32 + t];
            ss += s_pss[(c * 16 + i) * 32 + t];
        }
        const float mean = s * (1.f / 128.f);
        const float var  = ss * (1.f / 128.f) - mean * mean;
        s_mean[c * 32 + t] = mean;
        s_rstd[c * 32 + t] = rsqrtf(var + 1e-5f);
    }
    __syncthreads();

    // ---- P1c: reload (L2-hot) + normalize; kv -> bf16, q -> fp32 ------------
    {
        #pragma unroll
        for (int pass = 0; pass < 8; pass++) {
            const int d = pass * 16 + w;
            const float gkv = __ldg(ln_kv_g + d), bkv = __ldg(ln_kv_b + d);
            const float gq  = __ldg(ln_q_g + d),  bq_ = __ldg(ln_q_b + d);
            #pragma unroll
            for (int c = 0; c < 4; c++) {
                const float* src = h_all + (size_t)(c * Bb + b) * Dd * NTOK + tok0 + lane;
                const float v   = __ldg(src + (size_t)d * NTOK);
                const float nrm = (v - s_mean[c * 32 + lane]) * s_rstd[c * 32 + lane];
                s_x16[c * 4096 + d * 32 + lane] = f2bf(nrm * gkv + bkv);
                if (c == 0) s_xq[d * 32 + lane] = nrm * gq + bq_;
            }
        }
    }
    __syncthreads();

    const int og = w & 3;          // output-dim group (or head)
    const int t0 = (w >> 2) * 8;   // 8 tokens per warp

    // ---- P2: qfull[o][t] = LNq @ Wq_eff^T + bq_eff  (f32x2, LDS.128) --------
    {
        const int o = og * 32 + lane;
        const float bqv = g_bq[o];
        u64 a0 = pack2(bqv, bqv), a1 = a0, a2 = a0, a3 = a0;
        const float* wp = g_WqT + o;      // stride 128 over k
        const float* xp = s_xq + t0;
        #pragma unroll 4
        for (int kk = 0; kk < 128; kk++) {
            const float wv = wp[kk * 128];
            const u64 ww = pack2(wv, wv);
            const ulonglong2 xa = *(const ulonglong2*)(xp + kk * 32);
            const ulonglong2 xb = *(const ulonglong2*)(xp + kk * 32 + 4);
            a0 = ffma2(ww, xa.x, a0);
            a1 = ffma2(ww, xa.y, a1);
            a2 = ffma2(ww, xb.x, a2);
            a3 = ffma2(ww, xb.y, a3);
        }
        ulonglong2 o0; o0.x = a0; o0.y = a1;
        ulonglong2 o1; o1.x = a2; o1.y = a3;
        *(ulonglong2*)(s_qf + o * 32 + t0)     = o0;
        *(ulonglong2*)(s_qf + o * 32 + t0 + 4) = o1;
    }
    __syncthreads();

    // ---- P3: qk[h][j][t] = sum_i qfull[h*32+i][t] * Wk_eff[h*32+i][j] -------
    {
        const int h = og;
        u64 acc[4][4];
        #pragma unroll
        for (int m = 0; m < 4; m++)
            #pragma unroll
            for (int p = 0; p < 4; p++) acc[m][p] = 0ull;
        #pragma unroll 2
        for (int i = 0; i < 32; i++) {
            const int row = h * 32 + i;
            const float* wr = g_Wk + row * 128 + lane;
            const ulonglong2 xa = *(const ulonglong2*)(s_qf + row * 32 + t0);
            const ulonglong2 xb = *(const ulonglong2*)(s_qf + row * 32 + t0 + 4);
            #pragma unroll
            for (int m = 0; m < 4; m++) {
                const float wv = wr[m * 32];
                const u64 ww = pack2(wv, wv);
                acc[m][0] = ffma2(ww, xa.x, acc[m][0]);
                acc[m][1] = ffma2(ww, xa.y, acc[m][1]);
                acc[m][2] = ffma2(ww, xb.x, acc[m][2]);
                acc[m][3] = ffma2(ww, xb.y, acc[m][3]);
            }
        }
        #pragma unroll
        for (int m = 0; m < 4; m++) {
            const int j = lane + 32 * m;
            const float2 f0 = unpack2(acc[m][0]), f1 = unpack2(acc[m][1]);
            const float2 f2 = unpack2(acc[m][2]), f3 = unpack2(acc[m][3]);
            uint4 o4;
            o4.x = pack_bf16x2(f0.x, f0.y);
            o4.y = pack_bf16x2(f1.x, f1.y);
            o4.z = pack_bf16x2(f2.x, f2.y);
            o4.w = pack_bf16x2(f3.x, f3.y);
            *(uint4*)(s_qk16 + h * 4096 + j * 32 + t0) = o4;
        }
    }
    __syncthreads();

    // ---- P4: scores + softmax over c (k-bias provably cancels) --------------
    {
        const int t = tid & 31, idx = tid >> 5;
        const int h = idx & 3, c = idx >> 2;
        const unsigned short* qp = s_qk16 + h * 4096 + t;
        const unsigned short* xp = s_x16  + c * 4096 + t;
        float s = 0.f;
        #pragma unroll 8
        for (int j = 0; j < 128; j++) s += bf2f(qp[j * 32]) * bf2f(xp[j * 32]);
        s_sc[t * 16 + h * 4 + c] = s * 0.17677669529663687f;   // 1/sqrt(32)
    }
    __syncthreads();
    {
        const int t = tid & 31, idx = tid >> 5;
        const int h = idx & 3, c = idx >> 2;
        const float v0 = s_sc[t * 16 + h * 4 + 0];
        const float v1 = s_sc[t * 16 + h * 4 + 1];
        const float v2 = s_sc[t * 16 + h * 4 + 2];
        const float v3 = s_sc[t * 16 + h * 4 + 3];
        const float m  = fmaxf(fmaxf(v0, v1), fmaxf(v2, v3));
        const float e0 = __expf(v0 - m), e1 = __expf(v1 - m);
        const float e2 = __expf(v2 - m), e3 = __expf(v3 - m);
        const float inv = 1.f / (e0 + e1 + e2 + e3);
        const float mine = (c == 0 ? e0 : c == 1 ? e1 : c == 2 ? e2 : e3) * inv;
        __syncthreads();
        s_sc[t * 16 + h * 4 + c] = mine;
    }
    __syncthreads();

    // ---- P5: mix[h][j][t] = sum_c attn[t][h][c] * xkv[c][j][t]  (bf16 out) --
    {
        const int t = tid & 31, g = tid >> 5;
        #pragma unroll
        for (int h = 0; h < 4; h++) {
            const float a0 = s_sc[t * 16 + h * 4 + 0];
            const float a1 = s_sc[t * 16 + h * 4 + 1];
            const float a2 = s_sc[t * 16 + h * 4 + 2];
            const float a3 = s_sc[t * 16 + h * 4 + 3];
            #pragma unroll
            for (int jj = 0; jj < 8; jj++) {
                const int j = jj * 16 + g;
                const float mv = a0 * bf2f(s_x16[j * 32 + t])
                               + a1 * bf2f(s_x16[4096  + j * 32 + t])
                               + a2 * bf2f(s_x16[8192  + j * 32 + t])
                               + a3 * bf2f(s_x16[12288 + j * 32 + t]);
                s_qk16[h * 4096 + j * 32 + t] = f2bf(mv);
            }
        }
    }
    __syncthreads();

    // ---- P6: ctx[o][t] = mix[h=o/32] @ Wv_eff[o,:]^T + bv_eff (bf16 in) -----
    {
        const int o = og * 32 + lane;       // head = og
        const float bvv = g_bv[o];
        u64 a0 = pack2(bvv, bvv), a1 = a0, a2 = a0, a3 = a0;
        const float* wp = g_WvT + o;
        const unsigned short* xp = s_qk16 + og * 4096 + t0;
        #pragma unroll 4
        for (int j = 0; j < 128; j++) {
            const float wv = wp[j * 128];
            const u64 ww = pack2(wv, wv);
            const uint4 xv = *(const uint4*)(xp + j * 32);
            const u64 x0 = pack2(__uint_as_float(xv.x << 16), __uint_as_float(xv.x & 0xFFFF0000u));
            const u64 x1 = pack2(__uint_as_float(xv.y << 16), __uint_as_float(xv.y & 0xFFFF0000u));
            const u64 x2 = pack2(__uint_as_float(xv.z << 16), __uint_as_float(xv.z & 0xFFFF0000u));
            const u64 x3 = pack2(__uint_as_float(xv.w << 16), __uint_as_float(xv.w & 0xFFFF0000u));
            a0 = ffma2(ww, x0, a0);
            a1 = ffma2(ww, x1, a1);
            a2 = ffma2(ww, x2, a2);
            a3 = ffma2(ww, x3, a3);
        }
        ulonglong2 o0; o0.x = a0; o0.y = a1;
        ulonglong2 o1; o1.x = a2; o1.y = a3;
        *(ulonglong2*)(s_qf + o * 32 + t0)     = o0;   // overwrites qfull (done)
        *(ulonglong2*)(s_qf + o * 32 + t0 + 4) = o1;
    }
    __syncthreads();

    // ---- P7: staged[d][t] = ctx @ out_w^T + out_b  (residual added at store) -
    {
        const int d = og * 32 + lane;
        const float ob = __ldg(out_b + d);
        u64 a0 = pack2(ob, ob), a1 = a0, a2 = a0, a3 = a0;
        const float* wp = g_OwT + d;
        const float* xp = s_qf + t0;
        #pragma unroll 4
        for (int o = 0; o < 128; o++) {
            const float wv = wp[o * 128];
            const u64 ww = pack2(wv, wv);
            const ulonglong2 xa = *(const ulonglong2*)(xp + o * 32);
            const ulonglong2 xb = *(const ulonglong2*)(xp + o * 32 + 4);
            a0 = ffma2(ww, xa.x, a0);
            a1 = ffma2(ww, xa.y, a1);
            a2 = ffma2(ww, xb.x, a2);
            a3 = ffma2(ww, xb.y, a3);
        }
        ulonglong2 o0; o0.x = a0; o0.y = a1;
        ulonglong2 o1; o1.x = a2; o1.y = a3;
        *(ulonglong2*)(s_xq + d * 32 + t0)     = o0;   // overwrites xq (done)
        *(ulonglong2*)(s_xq + d * 32 + t0 + 4) = o1;
    }
    __syncthreads();

    // ---- writeout: add residual (re-read c0 raw, L2-likely) + coalesced STG -
    {
        const float* rsrc = h_all + (size_t)b * Dd * NTOK + tok0 + lane;   // c=0
        float* dstg = out + (size_t)b * Dd * NTOK + tok0 + lane;
        #pragma unroll
        for (int pass = 0; pass < 8; pass++) {
            const int d = pass * 16 + w;
            dstg[(size_t)d * NTOK] = s_xq[d * 32 + lane]
                                   + __ldg(rsrc + (size_t)d * NTOK);
        }
    }
}

// ---------------- launch ------------------------------------------------------
extern "C" void kernel_launch(void* const* d_in, const int* in_sizes, int n_in,
                              void* d_out, int out_size) {
    (void)in_sizes; (void)n_in; (void)out_size;
    const float* h_all   = (const float*)d_in[0];
    const float* ln_q_g  = (const float*)d_in[1];
    const float* ln_q_b  = (const float*)d_in[2];
    const float* ln_kv_g = (const float*)d_in[3];
    const float* ln_kv_b = (const float*)d_in[4];
    const float* Wq      = (const float*)d_in[5];
    const float* bq      = (const float*)d_in[6];
    const float* Wk      = (const float*)d_in[7];
    const float* bk      = (const float*)d_in[8];
    const float* Wv      = (const float*)d_in[9];
    const float* bv      = (const float*)d_in[10];
    const float* in_w    = (const float*)d_in[11];
    const float* in_b    = (const float*)d_in[12];
    const float* out_w   = (const float*)d_in[13];
    const float* out_b   = (const float*)d_in[14];
    float* out = (float*)d_out;

    prep_kernel<<<512, 128>>>(Wq, bq, Wk, bk, Wv, bv, in_w, in_b, out_w, out_b);

    const int smem_bytes = 25344 * sizeof(float);   // 101376 B -> 2 CTAs/SM
    cudaFuncSetAttribute(cca_main, cudaFuncAttributeMaxDynamicSharedMemorySize, smem_bytes);
    cca_main<<<NTILES, 512, smem_bytes>>>(h_all, ln_q_g, ln_q_b, ln_kv_g, ln_kv_b,
                                          out_b, out);
}

// round 13
// speedup vs baseline: 1.0011x; 1.0011x over previous
#include <cuda_runtime.h>
#include <cuda_bf16.h>
#include <cstdint>

// Problem constants
#define Cc 4
#define Bb 2
#define Dd 128
#define NTOK 65536          // F*T per batch
#define TOK 32              // tokens per CTA
#define NTILES 4096         // (Bb*NTOK)/TOK

typedef unsigned long long u64;

// ---------------- composed-weight scratch (device globals: no allocation) ----
__device__ float g_WqT[128 * 128];   // [k][o]  Wq_eff[o][k] = (in_w[0:128] @ Wq)[o][k]
__device__ float g_Wk [128 * 128];   // [r][k]  Wk_eff (row-major)
__device__ float g_WvT[128 * 128];   // [k][r]  Wv_eff transposed
__device__ float g_OwT[128 * 128];   // [o][d]  out_w transposed
__device__ float g_bq [128];         // composed q bias
__device__ float g_bv [128];         // composed v bias

// ---------------- f32x2 / bf16 helpers --------------------------------------
__device__ __forceinline__ u64 ffma2(u64 a, u64 b, u64 c) {
    u64 d;
    asm("fma.rn.f32x2 %0, %1, %2, %3;" : "=l"(d) : "l"(a), "l"(b), "l"(c));
    return d;
}
__device__ __forceinline__ u64 pack2(float lo, float hi) {
    u64 r;
    asm("mov.b64 %0, {%1, %2};" : "=l"(r) : "f"(lo), "f"(hi));
    return r;
}
__device__ __forceinline__ float2 unpack2(u64 v) {
    float2 r;
    asm("mov.b64 {%0, %1}, %2;" : "=f"(r.x), "=f"(r.y) : "l"(v));
    return r;
}
// cvt d, A, B -> d.lo = B, d.hi = A  (per ptx_helpers convention)
__device__ __forceinline__ unsigned pack_bf16x2(float lo, float hi) {
    unsigned r;
    asm("cvt.rn.bf16x2.f32 %0, %1, %2;" : "=r"(r) : "f"(hi), "f"(lo));
    return r;
}
__device__ __forceinline__ unsigned short f2bf(float f) {
    unsigned short h;
    asm("cvt.rn.bf16.f32 %0, %1;" : "=h"(h) : "f"(f));
    return h;
}
__device__ __forceinline__ float bf2f(unsigned short h) {
    return __uint_as_float(((unsigned)h) << 16);
}

// ---------------- prep: compose weights --------------------------------------
__global__ void prep_kernel(const float* __restrict__ Wq, const float* __restrict__ bq,
                            const float* __restrict__ Wk, const float* __restrict__ bk,
                            const float* __restrict__ Wv, const float* __restrict__ bv,
                            const float* __restrict__ in_w, const float* __restrict__ in_b,
                            const float* __restrict__ out_w, const float* __restrict__ out_b) {
    (void)bk; (void)out_b;
    const int blk = blockIdx.x;
    const int t = threadIdx.x;
    if (blk < 128) {
        const int o = blk;
        float acc = 0.f;
        #pragma unroll 8
        for (int m = 0; m < 128; m++) acc += in_w[o * 128 + m] * Wq[m * 128 + t];
        g_WqT[t * 128 + o] = acc;
        if (t == 0) {
            float s = in_b[o];
            for (int m = 0; m < 128; m++) s += in_w[o * 128 + m] * bq[m];
            g_bq[o] = s;
        }
    } else if (blk < 256) {
        const int r = blk - 128;
        float acc = 0.f;
        #pragma unroll 8
        for (int m = 0; m < 128; m++) acc += in_w[(128 + r) * 128 + m] * Wk[m * 128 + t];
        g_Wk[r * 128 + t] = acc;
    } else if (blk < 384) {
        const int r = blk - 256;
        float acc = 0.f;
        #pragma unroll 8
        for (int m = 0; m < 128; m++) acc += in_w[(256 + r) * 128 + m] * Wv[m * 128 + t];
        g_WvT[t * 128 + r] = acc;
        if (t == 0) {
            float s = in_b[256 + r];
            for (int m = 0; m < 128; m++) s += in_w[(256 + r) * 128 + m] * bv[m];
            g_bv[r] = s;
        }
    } else {
        const int d = blk - 384;
        g_OwT[t * 128 + d] = out_w[d * 128 + t];  // OwT[o][d]
    }
}

// ---------------- fused main kernel ------------------------------------------
// smem layout (25344 floats = 101376 B -> 2 CTAs/SM):
//  [0      .. 4096)   s_xq   fp32  q-normalized [d][t]  -> reused as staged out
//  [4096   .. 8192)   s_qf   fp32  qfull/ctx [o][t]     (aliased: LN partials)
//  [8192   .. 16384)  s_x16  bf16  normalized kv [c][d][t]  (16384 elems)
//  [16384  .. 24576)  s_qk16 bf16  qk / mix [h][j][t]       (16384 elems)
//  [24576  .. 25088)  s_sc   scores/attn [t][h][c]
//  [25088  .. 25216)  s_mean [c][t]
//  [25216  .. 25344)  s_rstd [c][t]
__global__ void __launch_bounds__(512, 2)
cca_main(const float* __restrict__ h_all,
         const float* __restrict__ ln_q_g, const float* __restrict__ ln_q_b,
         const float* __restrict__ ln_kv_g, const float* __restrict__ ln_kv_b,
         const float* __restrict__ out_b,
         float* __restrict__ out) {
    extern __shared__ float sm[];
    float* s_xq  = sm;
    float* s_qf  = sm + 4096;
    float* s_ps  = sm + 4096;                 // alias (dead before P2 writes s_qf)
    float* s_pss = sm + 6144;
    unsigned short* s_x16  = (unsigned short*)(sm + 8192);
    unsigned short* s_qk16 = (unsigned short*)(sm + 16384);
    float* s_sc   = sm + 24576;
    float* s_mean = sm + 25088;
    float* s_rstd = sm + 25216;

    const int tid  = threadIdx.x;
    const int w    = tid >> 5;
    const int lane = tid & 31;
    const int tile = blockIdx.x;
    const int b    = tile >> 11;            // 2048 tiles per batch element
    const int tok0 = (tile & 2047) * TOK;

    // ---- P1a: streaming partial LN stats (no raw staging) -------------------
    {
        #pragma unroll
        for (int c = 0; c < 4; c++) {
            const float* src = h_all + (size_t)(c * Bb + b) * Dd * NTOK + tok0 + lane;
            float s = 0.f, ss = 0.f;
            #pragma unroll
            for (int pass = 0; pass < 8; pass++) {
                const int d = pass * 16 + w;
                const float v = __ldg(src + (size_t)d * NTOK);
                s += v; ss += v * v;
            }
            s_ps [(c * 16 + w) * 32 + lane] = s;
            s_pss[(c * 16 + w) * 32 + lane] = ss;
        }
    }
    __syncthreads();

    // ---- P1b: finalize stats (biased variance, eps 1e-5) --------------------
    if (tid < 128) {
        const int c = tid >> 5, t = tid & 31;
        float s = 0.f, ss = 0.f;
        #pragma unroll
        for (int i = 0; i < 16; i++) {
            s  += s_ps [(c * 16 + i) * 32 + t];
            ss += s_pss[(c * 16 + i) * 32 + t];
        }
        const float mean = s * (1.f / 128.f);
        const float var  = ss * (1.f / 128.f) - mean * mean;
        s_mean[c * 32 + t] = mean;
        s_rstd[c * 32 + t] = rsqrtf(var + 1e-5f);
    }
    __syncthreads();

    // ---- P1c: reload (L2-hot) + normalize; kv -> bf16, q -> fp32 ------------
    {
        #pragma unroll
        for (int pass = 0; pass < 8; pass++) {
            const int d = pass * 16 + w;
            const float gkv = __ldg(ln_kv_g + d), bkv = __ldg(ln_kv_b + d);
            const float gq  = __ldg(ln_q_g + d),  bq_ = __ldg(ln_q_b + d);
            #pragma unroll
            for (int c = 0; c < 4; c++) {
                const float* src = h_all + (size_t)(c * Bb + b) * Dd * NTOK + tok0 + lane;
                const float v   = __ldg(src + (size_t)d * NTOK);
                const float nrm = (v - s_mean[c * 32 + lane]) * s_rstd[c * 32 + lane];
                s_x16[c * 4096 + d * 32 + lane] = f2bf(nrm * gkv + bkv);
                if (c == 0) s_xq[d * 32 + lane] = nrm * gq + bq_;
            }
        }
    }
    __syncthreads();

    const int og = w & 3;          // output-dim group (or head)
    const int t0 = (w >> 2) * 8;   // 8 tokens per warp

    // ---- P2: qfull[o][t] = LNq @ Wq_eff^T + bq_eff  (f32x2, LDS.128) --------
    {
        const int o = og * 32 + lane;
        const float bqv = g_bq[o];
        u64 a0 = pack2(bqv, bqv), a1 = a0, a2 = a0, a3 = a0;
        const float* wp = g_WqT + o;      // stride 128 over k
        const float* xp = s_xq + t0;
        #pragma unroll 4
        for (int kk = 0; kk < 128; kk++) {
            const float wv = wp[kk * 128];
            const u64 ww = pack2(wv, wv);
            const ulonglong2 xa = *(const ulonglong2*)(xp + kk * 32);
            const ulonglong2 xb = *(const ulonglong2*)(xp + kk * 32 + 4);
            a0 = ffma2(ww, xa.x, a0);
            a1 = ffma2(ww, xa.y, a1);
            a2 = ffma2(ww, xb.x, a2);
            a3 = ffma2(ww, xb.y, a3);
        }
        ulonglong2 o0; o0.x = a0; o0.y = a1;
        ulonglong2 o1; o1.x = a2; o1.y = a3;
        *(ulonglong2*)(s_qf + o * 32 + t0)     = o0;
        *(ulonglong2*)(s_qf + o * 32 + t0 + 4) = o1;
    }
    __syncthreads();

    // ---- P3: qk[h][j][t] = sum_i qfull[h*32+i][t] * Wk_eff[h*32+i][j] -------
    {
        const int h = og;
        u64 acc[4][4];
        #pragma unroll
        for (int m = 0; m < 4; m++)
            #pragma unroll
            for (int p = 0; p < 4; p++) acc[m][p] = 0ull;
        #pragma unroll 2
        for (int i = 0; i < 32; i++) {
            const int row = h * 32 + i;
            const float* wr = g_Wk + row * 128 + lane;
            const ulonglong2 xa = *(const ulonglong2*)(s_qf + row * 32 + t0);
            const ulonglong2 xb = *(const ulonglong2*)(s_qf + row * 32 + t0 + 4);
            #pragma unroll
            for (int m = 0; m < 4; m++) {
                const float wv = wr[m * 32];
                const u64 ww = pack2(wv, wv);
                acc[m][0] = ffma2(ww, xa.x, acc[m][0]);
                acc[m][1] = ffma2(ww, xa.y, acc[m][1]);
                acc[m][2] = ffma2(ww, xb.x, acc[m][2]);
                acc[m][3] = ffma2(ww, xb.y, acc[m][3]);
            }
        }
        #pragma unroll
        for (int m = 0; m < 4; m++) {
            const int j = lane + 32 * m;
            const float2 f0 = unpack2(acc[m][0]), f1 = unpack2(acc[m][1]);
            const float2 f2 = unpack2(acc[m][2]), f3 = unpack2(acc[m][3]);
            uint4 o4;
            o4.x = pack_bf16x2(f0.x, f0.y);
            o4.y = pack_bf16x2(f1.x, f1.y);
            o4.z = pack_bf16x2(f2.x, f2.y);
            o4.w = pack_bf16x2(f3.x, f3.y);
            *(uint4*)(s_qk16 + h * 4096 + j * 32 + t0) = o4;
        }
    }
    __syncthreads();

    // ---- P4: scores + softmax over c (k-bias provably cancels) --------------
    {
        const int t = tid & 31, idx = tid >> 5;
        const int h = idx & 3, c = idx >> 2;
        const unsigned short* qp = s_qk16 + h * 4096 + t;
        const unsigned short* xp = s_x16  + c * 4096 + t;
        float s = 0.f;
        #pragma unroll 8
        for (int j = 0; j < 128; j++) s += bf2f(qp[j * 32]) * bf2f(xp[j * 32]);
        s_sc[t * 16 + h * 4 + c] = s * 0.17677669529663687f;   // 1/sqrt(32)
    }
    __syncthreads();
    {
        const int t = tid & 31, idx = tid >> 5;
        const int h = idx & 3, c = idx >> 2;
        const float v0 = s_sc[t * 16 + h * 4 + 0];
        const float v1 = s_sc[t * 16 + h * 4 + 1];
        const float v2 = s_sc[t * 16 + h * 4 + 2];
        const float v3 = s_sc[t * 16 + h * 4 + 3];
        const float m  = fmaxf(fmaxf(v0, v1), fmaxf(v2, v3));
        const float e0 = __expf(v0 - m), e1 = __expf(v1 - m);
        const float e2 = __expf(v2 - m), e3 = __expf(v3 - m);
        const float inv = 1.f / (e0 + e1 + e2 + e3);
        const float mine = (c == 0 ? e0 : c == 1 ? e1 : c == 2 ? e2 : e3) * inv;
        __syncthreads();
        s_sc[t * 16 + h * 4 + c] = mine;
    }
    __syncthreads();

    // ---- P5: mix[h][j][t] = sum_c attn[t][h][c] * xkv[c][j][t]  (bf16 out) --
    {
        const int t = tid & 31, g = tid >> 5;
        #pragma unroll
        for (int h = 0; h < 4; h++) {
            const float a0 = s_sc[t * 16 + h * 4 + 0];
            const float a1 = s_sc[t * 16 + h * 4 + 1];
            const float a2 = s_sc[t * 16 + h * 4 + 2];
            const float a3 = s_sc[t * 16 + h * 4 + 3];
            #pragma unroll
            for (int jj = 0; jj < 8; jj++) {
                const int j = jj * 16 + g;
                const float mv = a0 * bf2f(s_x16[j * 32 + t])
                               + a1 * bf2f(s_x16[4096  + j * 32 + t])
                               + a2 * bf2f(s_x16[8192  + j * 32 + t])
                               + a3 * bf2f(s_x16[12288 + j * 32 + t]);
                s_qk16[h * 4096 + j * 32 + t] = f2bf(mv);
            }
        }
    }
    __syncthreads();

    // ---- P6: ctx[o][t] = mix[h=o/32] @ Wv_eff[o,:]^T + bv_eff (bf16 in) -----
    {
        const int o = og * 32 + lane;       // head = og
        const float bvv = g_bv[o];
        u64 a0 = pack2(bvv, bvv), a1 = a0, a2 = a0, a3 = a0;
        const float* wp = g_WvT + o;
        const unsigned short* xp = s_qk16 + og * 4096 + t0;
        #pragma unroll 4
        for (int j = 0; j < 128; j++) {
            const float wv = wp[j * 128];
            const u64 ww = pack2(wv, wv);
            const uint4 xv = *(const uint4*)(xp + j * 32);
            const u64 x0 = pack2(__uint_as_float(xv.x << 16), __uint_as_float(xv.x & 0xFFFF0000u));
            const u64 x1 = pack2(__uint_as_float(xv.y << 16), __uint_as_float(xv.y & 0xFFFF0000u));
            const u64 x2 = pack2(__uint_as_float(xv.z << 16), __uint_as_float(xv.z & 0xFFFF0000u));
            const u64 x3 = pack2(__uint_as_float(xv.w << 16), __uint_as_float(xv.w & 0xFFFF0000u));
            a0 = ffma2(ww, x0, a0);
            a1 = ffma2(ww, x1, a1);
            a2 = ffma2(ww, x2, a2);
            a3 = ffma2(ww, x3, a3);
        }
        ulonglong2 o0; o0.x = a0; o0.y = a1;
        ulonglong2 o1; o1.x = a2; o1.y = a3;
        *(ulonglong2*)(s_qf + o * 32 + t0)     = o0;   // overwrites qfull (done)
        *(ulonglong2*)(s_qf + o * 32 + t0 + 4) = o1;
    }
    __syncthreads();

    // ---- P7: staged[d][t] = ctx @ out_w^T + out_b  (residual added at store) -
    {
        const int d = og * 32 + lane;
        const float ob = __ldg(out_b + d);
        u64 a0 = pack2(ob, ob), a1 = a0, a2 = a0, a3 = a0;
        const float* wp = g_OwT + d;
        const float* xp = s_qf + t0;
        #pragma unroll 4
        for (int o = 0; o < 128; o++) {
            const float wv = wp[o * 128];
            const u64 ww = pack2(wv, wv);
            const ulonglong2 xa = *(const ulonglong2*)(xp + o * 32);
            const ulonglong2 xb = *(const ulonglong2*)(xp + o * 32 + 4);
            a0 = ffma2(ww, xa.x, a0);
            a1 = ffma2(ww, xa.y, a1);
            a2 = ffma2(ww, xb.x, a2);
            a3 = ffma2(ww, xb.y, a3);
        }
        ulonglong2 o0; o0.x = a0; o0.y = a1;
        ulonglong2 o1; o1.x = a2; o1.y = a3;
        *(ulonglong2*)(s_xq + d * 32 + t0)     = o0;   // overwrites xq (done)
        *(ulonglong2*)(s_xq + d * 32 + t0 + 4) = o1;
    }
    __syncthreads();

    // ---- writeout: add residual (re-read c0 raw, L2-likely) + coalesced STG -
    {
        const float* rsrc = h_all + (size_t)b * Dd * NTOK + tok0 + lane;   // c=0
        float* dstg = out + (size_t)b * Dd * NTOK + tok0 + lane;
        #pragma unroll
        for (int pass = 0; pass < 8; pass++) {
            const int d = pass * 16 + w;
            dstg[(size_t)d * NTOK] = s_xq[d * 32 + lane]
                                   + __ldg(rsrc + (size_t)d * NTOK);
        }
    }
}

// ---------------- launch ------------------------------------------------------
extern "C" void kernel_launch(void* const* d_in, const int* in_sizes, int n_in,
                              void* d_out, int out_size) {
    (void)in_sizes; (void)n_in; (void)out_size;
    const float* h_all   = (const float*)d_in[0];
    const float* ln_q_g  = (const float*)d_in[1];
    const float* ln_q_b  = (const float*)d_in[2];
    const float* ln_kv_g = (const float*)d_in[3];
    const float* ln_kv_b = (const float*)d_in[4];
    const float* Wq      = (const float*)d_in[5];
    const float* bq      = (const float*)d_in[6];
    const float* Wk      = (const float*)d_in[7];
    const float* bk      = (const float*)d_in[8];
    const float* Wv      = (const float*)d_in[9];
    const float* bv      = (const float*)d_in[10];
    const float* in_w    = (const float*)d_in[11];
    const float* in_b    = (const float*)d_in[12];
    const float* out_w   = (const float*)d_in[13];
    const float* out_b   = (const float*)d_in[14];
    float* out = (float*)d_out;

    prep_kernel<<<512, 128>>>(Wq, bq, Wk, bk, Wv, bv, in_w, in_b, out_w, out_b);

    const int smem_bytes = 25344 * sizeof(float);   // 101376 B -> 2 CTAs/SM
    cudaFuncSetAttribute(cca_main, cudaFuncAttributeMaxDynamicSharedMemorySize, smem_bytes);
    cca_main<<<NTILES, 512, smem_bytes>>>(h_all, ln_q_g, ln_q_b, ln_kv_g, ln_kv_b,
                                          out_b, out);
}

// round 14
// speedup vs baseline: 1.9610x; 1.9589x over previous
#include <cuda_runtime.h>
#include <cuda_bf16.h>
#include <cstdint>

#define Cc 4
#define Bb 2
#define Dd 128
#define NTOK 65536
#define TOK 32
#define NTILES 4096
#define XS 40               // token stride: 40 ≡ 8 (mod 32) -> conflict-free fragments

typedef unsigned long long u64;
typedef unsigned int u32;

// ---------------- device scratch ----------------------------------------------
__device__ float g_Wq_eff[128 * 128];   // [o][k]
__device__ float g_Wk_eff[128 * 128];   // [o][k]
__device__ float g_Wv_eff[128 * 128];   // [o][k]
__device__ float g_bq_eff[128];
__device__ float g_bv_eff[128];
__device__ float g_M  [4 * 128 * 128];  // fused qk weights per head: M_h[j][k]
__device__ float g_dk [4 * 128];        // fused qk bias per head
// fragment-packed A operands (tf32-rounded fp32 bits), layout [tile][lane][4]
__device__ float g_MA [4 * 8 * 16 * 128];   // (h, mt8, ks16)
__device__ float g_WvA[4 * 2 * 16 * 128];   // (h, mt2, ks16)
__device__ float g_OwA[8 * 16 * 128];       // (mt8, ks16)

// ---------------- helpers ------------------------------------------------------
__device__ __forceinline__ u32 f2tf32(float f) {
    u32 r; asm("cvt.rna.tf32.f32 %0, %1;" : "=r"(r) : "f"(f)); return r;
}
__device__ __forceinline__ unsigned pack_bf16x2(float lo, float hi) {
    unsigned r; asm("cvt.rn.bf16x2.f32 %0, %1, %2;" : "=r"(r) : "f"(hi), "f"(lo)); return r;
}
__device__ __forceinline__ unsigned short f2bf(float f) {
    unsigned short h; asm("cvt.rn.bf16.f32 %0, %1;" : "=h"(h) : "f"(f)); return h;
}
__device__ __forceinline__ float bf2f(unsigned short h) {
    return __uint_as_float(((unsigned)h) << 16);
}
__device__ __forceinline__ void mma_tf32(float* d, const uint4& a, u32 b0, u32 b1) {
    asm("mma.sync.aligned.m16n8k8.row.col.f32.tf32.tf32.f32 "
        "{%0,%1,%2,%3}, {%4,%5,%6,%7}, {%8,%9}, {%0,%1,%2,%3};"
        : "+f"(d[0]), "+f"(d[1]), "+f"(d[2]), "+f"(d[3])
        : "r"(a.x), "r"(a.y), "r"(a.z), "r"(a.w), "r"(b0), "r"(b1));
}

// ---------------- prep1a: compose base weights ---------------------------------
__global__ void prep1a(const float* __restrict__ Wq, const float* __restrict__ bq,
                       const float* __restrict__ Wk,
                       const float* __restrict__ Wv, const float* __restrict__ bv,
                       const float* __restrict__ in_w, const float* __restrict__ in_b) {
    const int blk = blockIdx.x, t = threadIdx.x;
    if (blk < 128) {
        const int o = blk;
        float acc = 0.f;
        #pragma unroll 8
        for (int m = 0; m < 128; m++) acc += in_w[o * 128 + m] * Wq[m * 128 + t];
        g_Wq_eff[o * 128 + t] = acc;
        if (t == 0) {
            float s = in_b[o];
            for (int m = 0; m < 128; m++) s += in_w[o * 128 + m] * bq[m];
            g_bq_eff[o] = s;
        }
    } else if (blk < 256) {
        const int o = blk - 128;
        float acc = 0.f;
        #pragma unroll 8
        for (int m = 0; m < 128; m++) acc += in_w[(128 + o) * 128 + m] * Wk[m * 128 + t];
        g_Wk_eff[o * 128 + t] = acc;
    } else {
        const int o = blk - 256;
        float acc = 0.f;
        #pragma unroll 8
        for (int m = 0; m < 128; m++) acc += in_w[(256 + o) * 128 + m] * Wv[m * 128 + t];
        g_Wv_eff[o * 128 + t] = acc;
        if (t == 0) {
            float s = in_b[256 + o];
            for (int m = 0; m < 128; m++) s += in_w[(256 + o) * 128 + m] * bv[m];
            g_bv_eff[o] = s;
        }
    }
}

// ---------------- prep1b: M_h = Wk_h^T @ Wq_eff_h ; d_h = Wk_h^T @ bq_h --------
__global__ void prep1b() {
    const int h = blockIdx.x >> 7, j = blockIdx.x & 127;
    const int k = threadIdx.x;
    float acc = 0.f;
    #pragma unroll 8
    for (int i = 0; i < 32; i++)
        acc += g_Wk_eff[(h * 32 + i) * 128 + j] * g_Wq_eff[(h * 32 + i) * 128 + k];
    g_M[h * 16384 + j * 128 + k] = acc;
    if (k == 0) {
        float s = 0.f;
        for (int i = 0; i < 32; i++)
            s += g_Wk_eff[(h * 32 + i) * 128 + j] * g_bq_eff[h * 32 + i];
        g_dk[h * 128 + j] = s;
    }
}

// ---------------- prep2: pack A fragments (m16k8, tf32-rounded) -----------------
__global__ void prep2(const float* __restrict__ out_w) {
    const int blk = blockIdx.x, lane = threadIdx.x;
    const int gid = lane >> 2, tig = lane & 3;
    const float* W; int r0; int b;
    float* dst;
    if (blk < 512) {                      // g_MA: h(4) x mt(8) x ks(16)
        const int h = blk >> 7, mt = (blk >> 4) & 7;
        W = g_M + h * 16384; r0 = mt * 16 + gid;
        dst = g_MA + blk * 128 + lane * 4; b = blk & 15;
    } else if (blk < 640) {               // g_WvA: h(4) x mt(2) x ks(16)
        const int bb2 = blk - 512;
        const int h = bb2 >> 5, mt = (bb2 >> 4) & 1;
        W = g_Wv_eff; r0 = h * 32 + mt * 16 + gid;
        dst = g_WvA + bb2 * 128 + lane * 4; b = bb2 & 15;
    } else {                              // g_OwA: mt(8) x ks(16)
        const int bb2 = blk - 640;
        const int mt = bb2 >> 4;
        W = out_w; r0 = mt * 16 + gid;
        dst = g_OwA + bb2 * 128 + lane * 4; b = bb2 & 15;
    }
    const int c0 = b * 8 + tig;
    dst[0] = __uint_as_float(f2tf32(W[r0 * 128 + c0]));
    dst[1] = __uint_as_float(f2tf32(W[(r0 + 8) * 128 + c0]));
    dst[2] = __uint_as_float(f2tf32(W[r0 * 128 + c0 + 4]));
    dst[3] = __uint_as_float(f2tf32(W[(r0 + 8) * 128 + c0 + 4]));
}

// ---------------- fused main kernel --------------------------------------------
// smem (26368 floats = 105472 B -> 2 CTAs/SM):
//  A    [0     .. 5120)   fp32 [128][XS]: xq(tf32) -> ctx(tf32)
//  x16  [5120  .. 15360)  bf16 [4][128][XS]: normalized kv
//  qk16 [15360 .. 25600)  bf16 [4][128][XS]: LN-partials -> qk -> mix -> out(fp32)
//  sc   [25600 .. 26112), mean [26112..26240), rstd [26240..26368)
__global__ void __launch_bounds__(512, 2)
cca_main(const float* __restrict__ h_all,
         const float* __restrict__ ln_q_g, const float* __restrict__ ln_q_b,
         const float* __restrict__ ln_kv_g, const float* __restrict__ ln_kv_b,
         const float* __restrict__ out_b,
         float* __restrict__ out) {
    extern __shared__ float sm[];
    float* s_af32 = sm;
    unsigned short* s_x16  = (unsigned short*)(sm + 5120);
    unsigned short* s_qk16 = (unsigned short*)(sm + 15360);
    float* s_ps   = sm + 15360;           // alias (dead before qk16 written)
    float* s_pss  = sm + 17408;
    float* s_out  = sm + 15360;           // alias (qk16 dead after P6)
    float* s_sc   = sm + 25600;
    float* s_mean = sm + 26112;
    float* s_rstd = sm + 26240;

    const int tid  = threadIdx.x;
    const int w    = tid >> 5;
    const int lane = tid & 31;
    const int gid  = lane >> 2, tig = lane & 3;
    const int tile = blockIdx.x;
    const int b    = tile >> 11;
    const int tok0 = (tile & 2047) * TOK;

    // ---- P1a: streaming partial LN stats ------------------------------------
    {
        #pragma unroll
        for (int c = 0; c < 4; c++) {
            const float* src = h_all + (size_t)(c * Bb + b) * Dd * NTOK + tok0 + lane;
            float s = 0.f, ss = 0.f;
            #pragma unroll
            for (int pass = 0; pass < 8; pass++) {
                const int d = pass * 16 + w;
                const float v = __ldg(src + (size_t)d * NTOK);
                s += v; ss += v * v;
            }
            s_ps [(c * 16 + w) * 32 + lane] = s;
            s_pss[(c * 16 + w) * 32 + lane] = ss;
        }
    }
    __syncthreads();

    // ---- P1b: finalize stats -------------------------------------------------
    if (tid < 128) {
        const int c = tid >> 5, t = tid & 31;
        float s = 0.f, ss = 0.f;
        #pragma unroll
        for (int i = 0; i < 16; i++) {
            s  += s_ps [(c * 16 + i) * 32 + t];
            ss += s_pss[(c * 16 + i) * 32 + t];
        }
        const float mean = s * (1.f / 128.f);
        const float var  = ss * (1.f / 128.f) - mean * mean;
        s_mean[c * 32 + t] = mean;
        s_rstd[c * 32 + t] = rsqrtf(var + 1e-5f);
    }
    __syncthreads();

    // ---- P1c: reload (L2-hot) + normalize; kv->bf16, q->tf32 fp32 ------------
    {
        #pragma unroll
        for (int pass = 0; pass < 8; pass++) {
            const int d = pass * 16 + w;
            const float gkv = __ldg(ln_kv_g + d), bkv = __ldg(ln_kv_b + d);
            const float gq  = __ldg(ln_q_g + d),  bq_ = __ldg(ln_q_b + d);
            #pragma unroll
            for (int c = 0; c < 4; c++) {
                const float* src = h_all + (size_t)(c * Bb + b) * Dd * NTOK + tok0 + lane;
                const float v   = __ldg(src + (size_t)d * NTOK);
                const float nrm = (v - s_mean[c * 32 + lane]) * s_rstd[c * 32 + lane];
                s_x16[(c * 128 + d) * XS + lane] = f2bf(nrm * gkv + bkv);
                if (c == 0)
                    s_af32[d * XS + lane] = __uint_as_float(f2tf32(nrm * gq + bq_));
            }
        }
    }
    __syncthreads();

    // ---- P23 (tensor): qk_h = M_h @ xq + d_h  -> bf16 qk16 -------------------
    {
        const int h = w >> 2, q = w & 3;
        #pragma unroll
        for (int mt2 = 0; mt2 < 2; mt2++) {
            const int mt = q * 2 + mt2;
            const float dk0 = g_dk[h * 128 + mt * 16 + gid];
            const float dk1 = g_dk[h * 128 + mt * 16 + gid + 8];
            float acc[4][4];
            #pragma unroll
            for (int nt = 0; nt < 4; nt++) {
                acc[nt][0] = dk0; acc[nt][1] = dk0;
                acc[nt][2] = dk1; acc[nt][3] = dk1;
            }
            const uint4* Ap = (const uint4*)(g_MA + ((h * 8 + mt) * 16) * 128) + lane;
            uint4 a = __ldg(Ap);
            #pragma unroll
            for (int ks = 0; ks < 16; ks++) {
                uint4 an;
                if (ks < 15) an = __ldg(Ap + (ks + 1) * 32);
                const float* xp = s_af32 + (ks * 8 + tig) * XS + gid;
                #pragma unroll
                for (int nt = 0; nt < 4; nt++) {
                    const u32 b0 = __float_as_uint(xp[nt * 8]);
                    const u32 b1 = __float_as_uint(xp[4 * XS + nt * 8]);
                    mma_tf32(acc[nt], a, b0, b1);
                }
                a = an;
            }
            const int j = mt * 16 + gid;
            #pragma unroll
            for (int nt = 0; nt < 4; nt++) {
                const int t = nt * 8 + 2 * tig;
                *(unsigned*)(s_qk16 + (h * 128 + j) * XS + t)     = pack_bf16x2(acc[nt][0], acc[nt][1]);
                *(unsigned*)(s_qk16 + (h * 128 + j + 8) * XS + t) = pack_bf16x2(acc[nt][2], acc[nt][3]);
            }
        }
    }
    __syncthreads();

    // ---- P4: scores + softmax over c ------------------------------------------
    {
        const int t = tid & 31, idx = tid >> 5;
        const int h = idx & 3, c = idx >> 2;
        const unsigned short* qp = s_qk16 + (h * 128) * XS + t;
        const unsigned short* xp = s_x16  + (c * 128) * XS + t;
        float s = 0.f;
        #pragma unroll 8
        for (int j = 0; j < 128; j++) s += bf2f(qp[j * XS]) * bf2f(xp[j * XS]);
        s_sc[t * 16 + h * 4 + c] = s * 0.17677669529663687f;   // 1/sqrt(32)
    }
    __syncthreads();
    {
        const int t = tid & 31, idx = tid >> 5;
        const int h = idx & 3, c = idx >> 2;
        const float v0 = s_sc[t * 16 + h * 4 + 0];
        const float v1 = s_sc[t * 16 + h * 4 + 1];
        const float v2 = s_sc[t * 16 + h * 4 + 2];
        const float v3 = s_sc[t * 16 + h * 4 + 3];
        const float m  = fmaxf(fmaxf(v0, v1), fmaxf(v2, v3));
        const float e0 = __expf(v0 - m), e1 = __expf(v1 - m);
        const float e2 = __expf(v2 - m), e3 = __expf(v3 - m);
        const float inv = 1.f / (e0 + e1 + e2 + e3);
        const float mine = (c == 0 ? e0 : c == 1 ? e1 : c == 2 ? e2 : e3) * inv;
        __syncthreads();
        s_sc[t * 16 + h * 4 + c] = mine;
    }
    __syncthreads();

    // ---- P5: mix[h][j][t] = sum_c attn[t][h][c] * xkv[c][j][t] -> qk16 -------
    {
        const int t = tid & 31, g = tid >> 5;
        #pragma unroll
        for (int h = 0; h < 4; h++) {
            const float a0 = s_sc[t * 16 + h * 4 + 0];
            const float a1 = s_sc[t * 16 + h * 4 + 1];
            const float a2 = s_sc[t * 16 + h * 4 + 2];
            const float a3 = s_sc[t * 16 + h * 4 + 3];
            #pragma unroll
            for (int jj = 0; jj < 8; jj++) {
                const int j = jj * 16 + g;
                const float mv = a0 * bf2f(s_x16[(0 * 128 + j) * XS + t])
                               + a1 * bf2f(s_x16[(1 * 128 + j) * XS + t])
                               + a2 * bf2f(s_x16[(2 * 128 + j) * XS + t])
                               + a3 * bf2f(s_x16[(3 * 128 + j) * XS + t]);
                s_qk16[(h * 128 + j) * XS + t] = f2bf(mv);
            }
        }
    }
    __syncthreads();

    // ---- P6 (tensor): ctx = Wv_h @ mix_h + bv -> tf32 fp32 in region A -------
    {
        const int h = w >> 2, sub = w & 3;
        const int mt = sub >> 1, nh = sub & 1;
        const float bv0 = g_bv_eff[h * 32 + mt * 16 + gid];
        const float bv1 = g_bv_eff[h * 32 + mt * 16 + gid + 8];
        float acc[2][4];
        #pragma unroll
        for (int n2 = 0; n2 < 2; n2++) {
            acc[n2][0] = bv0; acc[n2][1] = bv0;
            acc[n2][2] = bv1; acc[n2][3] = bv1;
        }
        const uint4* Ap = (const uint4*)(g_WvA + ((h * 2 + mt) * 16) * 128) + lane;
        uint4 a = __ldg(Ap);
        #pragma unroll
        for (int ks = 0; ks < 16; ks++) {
            uint4 an;
            if (ks < 15) an = __ldg(Ap + (ks + 1) * 32);
            const unsigned short* mp = s_qk16 + (h * 128 + ks * 8 + tig) * XS;
            #pragma unroll
            for (int n2 = 0; n2 < 2; n2++) {
                const int t = (nh * 2 + n2) * 8 + gid;
                const u32 b0 = ((u32)mp[t]) << 16;           // bf16 bits -> valid tf32
                const u32 b1 = ((u32)mp[4 * XS + t]) << 16;
                mma_tf32(acc[n2], a, b0, b1);
            }
            a = an;
        }
        const int o = h * 32 + mt * 16 + gid;
        #pragma unroll
        for (int n2 = 0; n2 < 2; n2++) {
            const int t = (nh * 2 + n2) * 8 + 2 * tig;
            s_af32[o * XS + t]           = __uint_as_float(f2tf32(acc[n2][0]));
            s_af32[o * XS + t + 1]       = __uint_as_float(f2tf32(acc[n2][1]));
            s_af32[(o + 8) * XS + t]     = __uint_as_float(f2tf32(acc[n2][2]));
            s_af32[(o + 8) * XS + t + 1] = __uint_as_float(f2tf32(acc[n2][3]));
        }
    }
    __syncthreads();

    // ---- P7 (tensor): out = out_w @ ctx + out_b -> s_out ----------------------
    {
        const int mt = w >> 1, nh = w & 1;
        const float ob0 = __ldg(out_b + mt * 16 + gid);
        const float ob1 = __ldg(out_b + mt * 16 + gid + 8);
        float acc[2][4];
        #pragma unroll
        for (int n2 = 0; n2 < 2; n2++) {
            acc[n2][0] = ob0; acc[n2][1] = ob0;
            acc[n2][2] = ob1; acc[n2][3] = ob1;
        }
        const uint4* Ap = (const uint4*)(g_OwA + (mt * 16) * 128) + lane;
        uint4 a = __ldg(Ap);
        #pragma unroll
        for (int ks = 0; ks < 16; ks++) {
            uint4 an;
            if (ks < 15) an = __ldg(Ap + (ks + 1) * 32);
            const float* cp = s_af32 + (ks * 8 + tig) * XS;
            #pragma unroll
            for (int n2 = 0; n2 < 2; n2++) {
                const int t = (nh * 2 + n2) * 8 + gid;
                const u32 b0 = __float_as_uint(cp[t]);
                const u32 b1 = __float_as_uint(cp[4 * XS + t]);
                mma_tf32(acc[n2], a, b0, b1);
            }
            a = an;
        }
        const int d = mt * 16 + gid;
        #pragma unroll
        for (int n2 = 0; n2 < 2; n2++) {
            const int t = (nh * 2 + n2) * 8 + 2 * tig;
            s_out[d * XS + t]           = acc[n2][0];
            s_out[d * XS + t + 1]       = acc[n2][1];
            s_out[(d + 8) * XS + t]     = acc[n2][2];
            s_out[(d + 8) * XS + t + 1] = acc[n2][3];
        }
    }
    __syncthreads();

    // ---- writeout: residual (re-read c0 raw) + coalesced STG ------------------
    {
        const float* rsrc = h_all + (size_t)b * Dd * NTOK + tok0 + lane;
        float* dstg = out + (size_t)b * Dd * NTOK + tok0 + lane;
        #pragma unroll
        for (int pass = 0; pass < 8; pass++) {
            const int d = pass * 16 + w;
            dstg[(size_t)d * NTOK] = s_out[d * XS + lane]
                                   + __ldg(rsrc + (size_t)d * NTOK);
        }
    }
}

// ---------------- launch --------------------------------------------------------
extern "C" void kernel_launch(void* const* d_in, const int* in_sizes, int n_in,
                              void* d_out, int out_size) {
    (void)in_sizes; (void)n_in; (void)out_size;
    const float* h_all   = (const float*)d_in[0];
    const float* ln_q_g  = (const float*)d_in[1];
    const float* ln_q_b  = (const float*)d_in[2];
    const float* ln_kv_g = (const float*)d_in[3];
    const float* ln_kv_b = (const float*)d_in[4];
    const float* Wq      = (const float*)d_in[5];
    const float* bq      = (const float*)d_in[6];
    const float* Wk      = (const float*)d_in[7];
    const float* bv_     = (const float*)d_in[10];
    const float* Wv      = (const float*)d_in[9];
    const float* in_w    = (const float*)d_in[11];
    const float* in_b    = (const float*)d_in[12];
    const float* out_w   = (const float*)d_in[13];
    const float* out_b   = (const float*)d_in[14];
    float* out = (float*)d_out;

    prep1a<<<384, 128>>>(Wq, bq, Wk, Wv, bv_, in_w, in_b);
    prep1b<<<512, 128>>>();
    prep2 <<<768, 32>>>(out_w);

    const int smem_bytes = 26368 * sizeof(float);   // 105472 B -> 2 CTAs/SM
    cudaFuncSetAttribute(cca_main, cudaFuncAttributeMaxDynamicSharedMemorySize, smem_bytes);
    cca_main<<<NTILES, 512, smem_bytes>>>(h_all, ln_q_g, ln_q_b, ln_kv_g, ln_kv_b,
                                          out_b, out);
}

// round 17
// speedup vs baseline: 2.2724x; 1.1588x over previous
#include <cuda_runtime.h>
#include <cuda_bf16.h>
#include <cstdint>

#define Bb 2
#define Dd 128
#define NTOK 65536
#define TOK 32
#define NTILES 4096
#define XS 40               // token row stride (floats/ushorts): 40 ≡ 8 (mod 32)
#define PX 5152             // plane stride for x16/qk16 in ushorts (128*XS + 32)

typedef unsigned long long u64;
typedef unsigned int u32;

// ---------------- device scratch ----------------------------------------------
__device__ float g_Wq_eff[128 * 128];   // [o][k]
__device__ float g_Wk_eff[128 * 128];   // [o][k]
__device__ float g_Wv_eff[128 * 128];   // [o][k]
__device__ float g_bq_eff[128];
__device__ float g_bv_eff[128];
__device__ float g_M  [4 * 128 * 128];  // fused qk weights per head: M_h[j][k]
__device__ float g_dk [4 * 128];        // fused qk bias per head
// fragment-packed A operands (tf32-rounded fp32 bits), layout [tile][lane][4]
__device__ float g_MA [4 * 8 * 16 * 128];   // (h, mt8, ks16)
__device__ float g_WvA[4 * 2 * 16 * 128];   // (h, mt2, ks16)
__device__ float g_OwA[8 * 16 * 128];       // (mt8, ks16)

// ---------------- helpers ------------------------------------------------------
__device__ __forceinline__ u32 f2tf32(float f) {
    u32 r; asm("cvt.rna.tf32.f32 %0, %1;" : "=r"(r) : "f"(f)); return r;
}
__device__ __forceinline__ unsigned pack_bf16x2(float lo, float hi) {
    unsigned r; asm("cvt.rn.bf16x2.f32 %0, %1, %2;" : "=r"(r) : "f"(hi), "f"(lo)); return r;
}
__device__ __forceinline__ unsigned short f2bf(float f) {
    unsigned short h; asm("cvt.rn.bf16.f32 %0, %1;" : "=h"(h) : "f"(f)); return h;
}
__device__ __forceinline__ float blo(u32 v) { return __uint_as_float(v << 16); }
__device__ __forceinline__ float bhi(u32 v) { return __uint_as_float(v & 0xFFFF0000u); }
__device__ __forceinline__ void mma_tf32(float* d, const uint4& a, u32 b0, u32 b1) {
    asm("mma.sync.aligned.m16n8k8.row.col.f32.tf32.tf32.f32 "
        "{%0,%1,%2,%3}, {%4,%5,%6,%7}, {%8,%9}, {%0,%1,%2,%3};"
        : "+f"(d[0]), "+f"(d[1]), "+f"(d[2]), "+f"(d[3])
        : "r"(a.x), "r"(a.y), "r"(a.z), "r"(a.w), "r"(b0), "r"(b1));
}

// ---------------- prep1a: compose base weights ---------------------------------
__global__ void prep1a(const float* __restrict__ Wq, const float* __restrict__ bq,
                       const float* __restrict__ Wk,
                       const float* __restrict__ Wv, const float* __restrict__ bv,
                       const float* __restrict__ in_w, const float* __restrict__ in_b) {
    const int blk = blockIdx.x, t = threadIdx.x;
    if (blk < 128) {
        const int o = blk;
        float acc = 0.f;
        #pragma unroll 8
        for (int m = 0; m < 128; m++) acc += in_w[o * 128 + m] * Wq[m * 128 + t];
        g_Wq_eff[o * 128 + t] = acc;
        if (t == 0) {
            float s = in_b[o];
            for (int m = 0; m < 128; m++) s += in_w[o * 128 + m] * bq[m];
            g_bq_eff[o] = s;
        }
    } else if (blk < 256) {
        const int o = blk - 128;
        float acc = 0.f;
        #pragma unroll 8
        for (int m = 0; m < 128; m++) acc += in_w[(128 + o) * 128 + m] * Wk[m * 128 + t];
        g_Wk_eff[o * 128 + t] = acc;
    } else {
        const int o = blk - 256;
        float acc = 0.f;
        #pragma unroll 8
        for (int m = 0; m < 128; m++) acc += in_w[(256 + o) * 128 + m] * Wv[m * 128 + t];
        g_Wv_eff[o * 128 + t] = acc;
        if (t == 0) {
            float s = in_b[256 + o];
            for (int m = 0; m < 128; m++) s += in_w[(256 + o) * 128 + m] * bv[m];
            g_bv_eff[o] = s;
        }
    }
}

// ---------------- prep1b: M_h = Wk_h^T @ Wq_eff_h ; d_h = Wk_h^T @ bq_h --------
__global__ void prep1b() {
    const int h = blockIdx.x >> 7, j = blockIdx.x & 127;
    const int k = threadIdx.x;
    float acc = 0.f;
    #pragma unroll 8
    for (int i = 0; i < 32; i++)
        acc += g_Wk_eff[(h * 32 + i) * 128 + j] * g_Wq_eff[(h * 32 + i) * 128 + k];
    g_M[h * 16384 + j * 128 + k] = acc;
    if (k == 0) {
        float s = 0.f;
        for (int i = 0; i < 32; i++)
            s += g_Wk_eff[(h * 32 + i) * 128 + j] * g_bq_eff[h * 32 + i];
        g_dk[h * 128 + j] = s;
    }
}

// ---------------- prep2: pack A fragments (m16k8, tf32-rounded) -----------------
__global__ void prep2(const float* __restrict__ out_w) {
    const int blk = blockIdx.x, lane = threadIdx.x;
    const int gid = lane >> 2, tig = lane & 3;
    const float* W; int r0; int b;
    float* dst;
    if (blk < 512) {                      // g_MA: h(4) x mt(8) x ks(16)
        const int h = blk >> 7, mt = (blk >> 4) & 7;
        W = g_M + h * 16384; r0 = mt * 16 + gid;
        dst = g_MA + blk * 128 + lane * 4; b = blk & 15;
    } else if (blk < 640) {               // g_WvA: h(4) x mt(2) x ks(16)
        const int bb2 = blk - 512;
        const int h = bb2 >> 5, mt = (bb2 >> 4) & 1;
        W = g_Wv_eff; r0 = h * 32 + mt * 16 + gid;
        dst = g_WvA + bb2 * 128 + lane * 4; b = bb2 & 15;
    } else {                              // g_OwA: mt(8) x ks(16)
        const int bb2 = blk - 640;
        const int mt = bb2 >> 4;
        W = out_w; r0 = mt * 16 + gid;
        dst = g_OwA + bb2 * 128 + lane * 4; b = bb2 & 15;
    }
    const int c0 = b * 8 + tig;
    dst[0] = __uint_as_float(f2tf32(W[r0 * 128 + c0]));
    dst[1] = __uint_as_float(f2tf32(W[(r0 + 8) * 128 + c0]));
    dst[2] = __uint_as_float(f2tf32(W[r0 * 128 + c0 + 4]));
    dst[3] = __uint_as_float(f2tf32(W[(r0 + 8) * 128 + c0 + 4]));
}

// ---------------- fused main kernel --------------------------------------------
// smem (27008 floats = 108032 B -> 2 CTAs/SM):
//  AF   [0     .. 5120)   fp32 [128][XS]: xq(tf32) -> P4 partials -> ctx(tf32)
//  X16  [5120  .. 15424)  bf16 4 planes of PX: normalized kv
//  QK16 [15424 .. 25728)  bf16 4 planes of PX: LN-partials -> qk -> mix -> out(fp32)
//  SC   [25728 .. 26240)  scores [t][h][c]
//  SCT  [26240 .. 26752)  attn   [h][c][t]
//  MEAN [26752..26880), RSTD [26880..27008)
__global__ void __launch_bounds__(512, 2)
cca_main(const float* __restrict__ h_all,
         const float* __restrict__ ln_q_g, const float* __restrict__ ln_q_b,
         const float* __restrict__ ln_kv_g, const float* __restrict__ ln_kv_b,
         const float* __restrict__ out_b,
         float* __restrict__ out) {
    extern __shared__ float sm[];
    float* s_af32 = sm;
    unsigned short* s_x16  = (unsigned short*)(sm + 5120);
    unsigned short* s_qk16 = (unsigned short*)(sm + 15424);
    float* s_ps   = sm + 15424;           // alias (dead before qk16 written)
    float* s_pss  = sm + 17472;
    float* s_out  = sm + 15424;           // alias (mix dead after P6)
    float* s_part = sm;                   // alias (xq dead after P23)
    float* s_sc   = sm + 25728;
    float* s_scT  = sm + 26240;
    float* s_mean = sm + 26752;
    float* s_rstd = sm + 26880;

    const int tid  = threadIdx.x;
    const int w    = tid >> 5;
    const int lane = tid & 31;
    const int gid  = lane >> 2, tig = lane & 3;
    const int tile = blockIdx.x;
    const int b    = tile >> 11;
    const int tok0 = (tile & 2047) * TOK;

    // ---- P1a: streaming partial LN stats ------------------------------------
    {
        #pragma unroll
        for (int c = 0; c < 4; c++) {
            const float* src = h_all + (size_t)(c * Bb + b) * Dd * NTOK + tok0 + lane;
            float s = 0.f, ss = 0.f;
            #pragma unroll
            for (int pass = 0; pass < 8; pass++) {
                const int d = pass * 16 + w;
                const float v = __ldg(src + (size_t)d * NTOK);
                s += v; ss += v * v;
            }
            s_ps [(c * 16 + w) * 32 + lane] = s;
            s_pss[(c * 16 + w) * 32 + lane] = ss;
        }
    }
    __syncthreads();

    // ---- P1b: finalize stats -------------------------------------------------
    if (tid < 128) {
        const int c = tid >> 5, t = tid & 31;
        float s = 0.f, ss = 0.f;
        #pragma unroll
        for (int i = 0; i < 16; i++) {
            s  += s_ps [(c * 16 + i) * 32 + t];
            ss += s_pss[(c * 16 + i) * 32 + t];
        }
        const float mean = s * (1.f / 128.f);
        const float var  = ss * (1.f / 128.f) - mean * mean;
        s_mean[c * 32 + t] = mean;
        s_rstd[c * 32 + t] = rsqrtf(var + 1e-5f);
    }
    __syncthreads();

    // ---- P1c: reload (L2-hot) + normalize; kv->bf16, q->tf32 fp32 ------------
    {
        #pragma unroll
        for (int pass = 0; pass < 8; pass++) {
            const int d = pass * 16 + w;
            const float gkv = __ldg(ln_kv_g + d), bkv = __ldg(ln_kv_b + d);
            const float gq  = __ldg(ln_q_g + d),  bq_ = __ldg(ln_q_b + d);
            #pragma unroll
            for (int c = 0; c < 4; c++) {
                const float* src = h_all + (size_t)(c * Bb + b) * Dd * NTOK + tok0 + lane;
                const float v   = __ldg(src + (size_t)d * NTOK);
                const float nrm = (v - s_mean[c * 32 + lane]) * s_rstd[c * 32 + lane];
                s_x16[c * PX + d * XS + lane] = f2bf(nrm * gkv + bkv);
                if (c == 0)
                    s_af32[d * XS + lane] = __uint_as_float(f2tf32(nrm * gq + bq_));
            }
        }
    }
    __syncthreads();

    // ---- P23 (tensor): qk_h = M_h @ xq + d_h ; ks-outer, B shared over 2 mt --
    {
        const int h = w >> 2, q = w & 3;
        const int mt0 = q * 2, mt1 = q * 2 + 1;
        float acc0[4][4], acc1[4][4];
        {
            const float d00 = g_dk[h * 128 + mt0 * 16 + gid];
            const float d01 = g_dk[h * 128 + mt0 * 16 + gid + 8];
            const float d10 = g_dk[h * 128 + mt1 * 16 + gid];
            const float d11 = g_dk[h * 128 + mt1 * 16 + gid + 8];
            #pragma unroll
            for (int nt = 0; nt < 4; nt++) {
                acc0[nt][0] = d00; acc0[nt][1] = d00; acc0[nt][2] = d01; acc0[nt][3] = d01;
                acc1[nt][0] = d10; acc1[nt][1] = d10; acc1[nt][2] = d11; acc1[nt][3] = d11;
            }
        }
        const uint4* Ap0 = (const uint4*)(g_MA + ((h * 8 + mt0) * 16) * 128) + lane;
        const uint4* Ap1 = (const uint4*)(g_MA + ((h * 8 + mt1) * 16) * 128) + lane;
        #pragma unroll
        for (int ks = 0; ks < 16; ks++) {
            const uint4 a0 = __ldg(Ap0 + ks * 32);
            const uint4 a1 = __ldg(Ap1 + ks * 32);
            const float* xp = s_af32 + (ks * 8 + tig) * XS + gid;
            u32 b0[4], b1[4];
            #pragma unroll
            for (int nt = 0; nt < 4; nt++) {
                b0[nt] = __float_as_uint(xp[nt * 8]);
                b1[nt] = __float_as_uint(xp[4 * XS + nt * 8]);
            }
            #pragma unroll
            for (int nt = 0; nt < 4; nt++) {
                mma_tf32(acc0[nt], a0, b0[nt], b1[nt]);
                mma_tf32(acc1[nt], a1, b0[nt], b1[nt]);
            }
        }
        #pragma unroll
        for (int nt = 0; nt < 4; nt++) {
            const int t = nt * 8 + 2 * tig;
            const int j0 = mt0 * 16 + gid, j1 = mt1 * 16 + gid;
            *(unsigned*)(s_qk16 + h * PX + j0 * XS + t)        = pack_bf16x2(acc0[nt][0], acc0[nt][1]);
            *(unsigned*)(s_qk16 + h * PX + (j0 + 8) * XS + t)  = pack_bf16x2(acc0[nt][2], acc0[nt][3]);
            *(unsigned*)(s_qk16 + h * PX + j1 * XS + t)        = pack_bf16x2(acc1[nt][0], acc1[nt][1]);
            *(unsigned*)(s_qk16 + h * PX + (j1 + 8) * XS + t)  = pack_bf16x2(acc1[nt][2], acc1[nt][3]);
        }
    }
    __syncthreads();

    // ---- P4: score partials (vectorized LDS.64, j split over 4 warps/head) ---
    {
        const int h = w & 3, jseg = w >> 2;
        const int c = lane >> 3, tg = lane & 7;
        const unsigned short* qp = s_qk16 + h * PX + (jseg * 32) * XS + 4 * tg;
        const unsigned short* xp = s_x16  + c * PX + (jseg * 32) * XS + 4 * tg;
        float a0 = 0.f, a1 = 0.f, a2 = 0.f, a3 = 0.f;
        #pragma unroll 8
        for (int i = 0; i < 32; i++) {
            const uint2 qq = *(const uint2*)(qp + i * XS);
            const uint2 xx = *(const uint2*)(xp + i * XS);
            a0 += blo(qq.x) * blo(xx.x);
            a1 += bhi(qq.x) * bhi(xx.x);
            a2 += blo(qq.y) * blo(xx.y);
            a3 += bhi(qq.y) * bhi(xx.y);
        }
        float4 p; p.x = a0; p.y = a1; p.z = a2; p.w = a3;
        *(float4*)(s_part + jseg * 512 + (h * 4 + c) * 32 + tg * 4) = p;
    }
    __syncthreads();

    // ---- P4b: reduce partials -> scores --------------------------------------
    {
        const int hc = tid >> 5, t = tid & 31;
        const float s = s_part[hc * 32 + t] + s_part[512 + hc * 32 + t]
                      + s_part[1024 + hc * 32 + t] + s_part[1536 + hc * 32 + t];
        const int h = hc >> 2, c = hc & 3;
        s_sc[t * 16 + h * 4 + c] = s * 0.17677669529663687f;   // 1/sqrt(32)
    }
    __syncthreads();

    // ---- P4c: softmax over c -> transposed attn s_scT[h][c][t] ---------------
    {
        const int t = tid & 31, idx = tid >> 5;
        const int h = idx & 3, c = idx >> 2;
        const float4 v = *(const float4*)(s_sc + t * 16 + h * 4);
        const float m  = fmaxf(fmaxf(v.x, v.y), fmaxf(v.z, v.w));
        const float e0 = __expf(v.x - m), e1 = __expf(v.y - m);
        const float e2 = __expf(v.z - m), e3 = __expf(v.w - m);
        const float inv = 1.f / (e0 + e1 + e2 + e3);
        const float mine = (c == 0 ? e0 : c == 1 ? e1 : c == 2 ? e2 : e3) * inv;
        s_scT[(h * 4 + c) * 32 + t] = mine;
    }
    __syncthreads();

    // ---- P5: mix[h][j][t] = sum_c attn * x ; x broadcast over 4 head-lanes ---
    {
        const int jb = w * 8;
        const int h = lane >> 3, tp = lane & 7;
        float at[4][4];
        #pragma unroll
        for (int c = 0; c < 4; c++)
            *(float4*)at[c] = *(const float4*)(s_scT + (h * 4 + c) * 32 + 4 * tp);
        #pragma unroll
        for (int jj = 0; jj < 8; jj++) {
            const int j = jb + jj;
            float m0 = 0.f, m1 = 0.f, m2 = 0.f, m3 = 0.f;
            #pragma unroll
            for (int c = 0; c < 4; c++) {
                const uint2 xx = *(const uint2*)(s_x16 + c * PX + j * XS + 4 * tp);
                m0 += at[c][0] * blo(xx.x);
                m1 += at[c][1] * bhi(xx.x);
                m2 += at[c][2] * blo(xx.y);
                m3 += at[c][3] * bhi(xx.y);
            }
            uint2 o;
            o.x = pack_bf16x2(m0, m1);
            o.y = pack_bf16x2(m2, m3);
            *(uint2*)(s_qk16 + h * PX + j * XS + 4 * tp) = o;
        }
    }
    __syncthreads();

    // ---- P6 (tensor): ctx = Wv_h @ mix_h + bv -> tf32 fp32 in AF -------------
    {
        const int h = w >> 2, sub = w & 3;
        const int mt = sub >> 1, nh = sub & 1;
        const float bv0 = g_bv_eff[h * 32 + mt * 16 + gid];
        const float bv1 = g_bv_eff[h * 32 + mt * 16 + gid + 8];
        float acc[2][4];
        #pragma unroll
        for (int n2 = 0; n2 < 2; n2++) {
            acc[n2][0] = bv0; acc[n2][1] = bv0;
            acc[n2][2] = bv1; acc[n2][3] = bv1;
        }
        const uint4* Ap = (const uint4*)(g_WvA + ((h * 2 + mt) * 16) * 128) + lane;
        #pragma unroll
        for (int ks = 0; ks < 16; ks++) {
            const uint4 a = __ldg(Ap + ks * 32);
            const unsigned short* mp = s_qk16 + h * PX + (ks * 8 + tig) * XS;
            #pragma unroll
            for (int n2 = 0; n2 < 2; n2++) {
                const int t = (nh * 2 + n2) * 8 + gid;
                const u32 b0 = ((u32)mp[t]) << 16;           // bf16 bits -> valid tf32
                const u32 b1 = ((u32)mp[4 * XS + t]) << 16;
                mma_tf32(acc[n2], a, b0, b1);
            }
        }
        const int o = h * 32 + mt * 16 + gid;
        #pragma unroll
        for (int n2 = 0; n2 < 2; n2++) {
            const int t = (nh * 2 + n2) * 8 + 2 * tig;
            s_af32[o * XS + t]           = __uint_as_float(f2tf32(acc[n2][0]));
            s_af32[o * XS + t + 1]       = __uint_as_float(f2tf32(acc[n2][1]));
            s_af32[(o + 8) * XS + t]     = __uint_as_float(f2tf32(acc[n2][2]));
            s_af32[(o + 8) * XS + t + 1] = __uint_as_float(f2tf32(acc[n2][3]));
        }
    }
    __syncthreads();

    // ---- P7 (tensor): out = out_w @ ctx + out_b -> s_out ----------------------
    {
        const int mt = w >> 1, nh = w & 1;
        const float ob0 = __ldg(out_b + mt * 16 + gid);
        const float ob1 = __ldg(out_b + mt * 16 + gid + 8);
        float acc[2][4];
        #pragma unroll
        for (int n2 = 0; n2 < 2; n2++) {
            acc[n2][0] = ob0; acc[n2][1] = ob0;
            acc[n2][2] = ob1; acc[n2][3] = ob1;
        }
        const uint4* Ap = (const uint4*)(g_OwA + (mt * 16) * 128) + lane;
        #pragma unroll
        for (int ks = 0; ks < 16; ks++) {
            const uint4 a = __ldg(Ap + ks * 32);
            const float* cp = s_af32 + (ks * 8 + tig) * XS;
            #pragma unroll
            for (int n2 = 0; n2 < 2; n2++) {
                const int t = (nh * 2 + n2) * 8 + gid;
                const u32 b0 = __float_as_uint(cp[t]);
                const u32 b1 = __float_as_uint(cp[4 * XS + t]);
                mma_tf32(acc[n2], a, b0, b1);
            }
        }
        const int d = mt * 16 + gid;
        #pragma unroll
        for (int n2 = 0; n2 < 2; n2++) {
            const int t = (nh * 2 + n2) * 8 + 2 * tig;
            s_out[d * XS + t]           = acc[n2][0];
            s_out[d * XS + t + 1]       = acc[n2][1];
            s_out[(d + 8) * XS + t]     = acc[n2][2];
            s_out[(d + 8) * XS + t + 1] = acc[n2][3];
        }
    }
    __syncthreads();

    // ---- writeout: residual (re-read c0 raw) + coalesced STG ------------------
    {
        const float* rsrc = h_all + (size_t)b * Dd * NTOK + tok0 + lane;
        float* dstg = out + (size_t)b * Dd * NTOK + tok0 + lane;
        #pragma unroll
        for (int pass = 0; pass < 8; pass++) {
            const int d = pass * 16 + w;
            dstg[(size_t)d * NTOK] = s_out[d * XS + lane]
                                   + __ldg(rsrc + (size_t)d * NTOK);
        }
    }
}

// ---------------- launch --------------------------------------------------------
extern "C" void kernel_launch(void* const* d_in, const int* in_sizes, int n_in,
                              void* d_out, int out_size) {
    (void)in_sizes; (void)n_in; (void)out_size;
    const float* h_all   = (const float*)d_in[0];
    const float* ln_q_g  = (const float*)d_in[1];
    const float* ln_q_b  = (const float*)d_in[2];
    const float* ln_kv_g = (const float*)d_in[3];
    const float* ln_kv_b = (const float*)d_in[4];
    const float* Wq      = (const float*)d_in[5];
    const float* bq      = (const float*)d_in[6];
    const float* Wk      = (const float*)d_in[7];
    const float* Wv      = (const float*)d_in[9];
    const float* bv_     = (const float*)d_in[10];
    const float* in_w    = (const float*)d_in[11];
    const float* in_b    = (const float*)d_in[12];
    const float* out_w   = (const float*)d_in[13];
    const float* out_b   = (const float*)d_in[14];
    float* out = (float*)d_out;

    prep1a<<<384, 128>>>(Wq, bq, Wk, Wv, bv_, in_w, in_b);
    prep1b<<<512, 128>>>();
    prep2 <<<768, 32>>>(out_w);

    const int smem_bytes = 27008 * sizeof(float);   // 108032 B -> 2 CTAs/SM
    cudaFuncSetAttribute(cca_main, cudaFuncAttributeMaxDynamicSharedMemorySize, smem_bytes);
    cca_main<<<NTILES, 512, smem_bytes>>>(h_all, ln_q_g, ln_q_b, ln_kv_g, ln_kv_b,
                                          out_b, out);
}